// round 14
// baseline (speedup 1.0000x reference)
#include <cuda_runtime.h>

typedef unsigned long long u64;

// ---- packed f32x2 helpers (Blackwell sm_103a) ----
__device__ __forceinline__ u64 pk2(float a, float b) {
    u64 r; asm("mov.b64 %0,{%1,%2};" : "=l"(r) : "f"(a), "f"(b)); return r;
}
__device__ __forceinline__ void fma2(u64 &d, u64 a, u64 b) {
    asm("fma.rn.f32x2 %0,%1,%2,%0;" : "+l"(d) : "l"(a), "l"(b));
}
__device__ __forceinline__ u64 mul2(u64 a, u64 b) {
    u64 r; asm("mul.rn.f32x2 %0,%1,%2;" : "=l"(r) : "l"(a), "l"(b)); return r;
}
__device__ __forceinline__ u64 add2(u64 a, u64 b) {
    u64 r; asm("add.rn.f32x2 %0,%1,%2;" : "=l"(r) : "l"(a), "l"(b)); return r;
}
__device__ __forceinline__ void up2(u64 v, float &x, float &y) {
    asm("mov.b64 {%0,%1},%2;" : "=f"(x), "=f"(y) : "l"(v));
}
__device__ __forceinline__ void cp8(unsigned sa, const float2* ga) {
    asm volatile("cp.async.ca.shared.global [%0],[%1],8;" :: "r"(sa), "l"(ga));
}
__device__ __forceinline__ void cp_commit() {
    asm volatile("cp.async.commit_group;");
}
__device__ __forceinline__ void cp_wait1() {
    asm volatile("cp.async.wait_group 1;");
}

// Shapes: x:(64,4,2,256,256) w:(4,4,128,128,16,2) bias:(4,128,128,2) out:(64,4,2,128,128)
#define NCHUNK 2
#define NPC (64 / NCHUNK)     // 32 n per block
#define XBUF 256              // float2 per x slice: 16 planes (c,i,r) * 16 y = 2 KB
#define NBUF 16               // ring depth (slices), 32 KB
#define NSTR 262144           // per-n stride in x, float2 units

// Block = 128 threads = 4 warps, 5 blocks/SM.
//   warp = ph*2 + wy: ph = p-pair (p in {2ph, 2ph+1}), wy = y-half.
//   lane = c*8 + dy; y = y0 + wy*8 + dy (y-tile of 16).
// Each (c,y) is read by only 2 threads (the two ph warps) -> 2x smem-read
// amplification instead of 4x; patch products serve 2 fma trees.
// Grid = 128 (x) * 8 (y-tile) * 2 (nch in bid bit 0 -> weight L2 pairing) = 2048.
__global__ void __launch_bounds__(128, 5) ttn_kernel(
    const float* __restrict__ X, const float* __restrict__ W,
    const float* __restrict__ B, float* __restrict__ O)
{
    __shared__ __align__(16) float4 smw[512];            // 8 KB weight staging
    __shared__ __align__(16) float2 xsm[NBUF * XBUF];    // 32 KB x ring

    const int tid  = threadIdx.x;
    const int warp = tid >> 5;
    const int lane = tid & 31;
    const int c    = lane >> 3;
    const int dy   = lane & 7;
    const int ph   = warp >> 1;        // p-pair
    const int wy   = warp & 1;         // y-half

    const int bid = blockIdx.x;
    const int nch = bid & 1;           // adjacent bids share weights -> L2 hit
    const int xp  = bid >> 4;
    const int y0  = ((bid >> 1) & 7) * 16;
    const int n0  = nch * NPC;
    const int yv  = wy * 8 + dy;       // local y (0..15)
    const int y   = y0 + yv;

    // ---- x staging: 2 float2 per thread per slice ----
    // F -> plane pl=F>>4 (c_,i_,r_), yc=F&15; swizzle sw(c)=((c&1)<<3)|((c>>1)<<1)
    const int F0 = tid, F1 = tid + 128;
    const int pl0 = F0 >> 4, yc0 = F0 & 15;
    const int pl1 = F1 >> 4, yc1 = F1 & 15;
    const int c0_ = pl0 >> 2, i0_ = (pl0 >> 1) & 1, r0_ = pl0 & 1;
    const int c1_ = pl1 >> 2, i1_ = (pl1 >> 1) & 1, r1_ = pl1 & 1;
    const int sw0 = ((c0_ & 1) << 3) | ((c0_ >> 1) << 1);
    const int sw1 = ((c1_ & 1) << 3) | ((c1_ >> 1) << 1);
    const int goff0 = (c0_ * 2 + i0_) * 32768 + (2 * xp + r0_) * 128 + y0 + yc0;
    const int goff1 = (c1_ * 2 + i1_) * 32768 + (2 * xp + r1_) * 128 + y0 + yc1;
    const int soff0 = pl0 * 16 + (yc0 ^ sw0);
    const int soff1 = pl1 * 16 + (yc1 ^ sw1);

    unsigned sbase = (unsigned)__cvta_generic_to_shared(xsm);
    unsigned sa0   = sbase + (unsigned)soff0 * 8u;
    unsigned sa1   = sbase + (unsigned)soff1 * 8u;

    // prologue: slices 0..7 as two 4-slice groups (overlap weight staging)
    {
        const float2* g0 = (const float2*)X + (long)n0 * NSTR + goff0;
        const float2* g1 = (const float2*)X + (long)n0 * NSTR + goff1;
#pragma unroll
        for (int s = 0; s < 4; ++s) {
            cp8(sa0 + (unsigned)s * XBUF * 8u, g0 + (long)s * NSTR);
            cp8(sa1 + (unsigned)s * XBUF * 8u, g1 + (long)s * NSTR);
        }
        cp_commit();
#pragma unroll
        for (int s = 4; s < 8; ++s) {
            cp8(sa0 + (unsigned)s * XBUF * 8u, g0 + (long)s * NSTR);
            cp8(sa1 + (unsigned)s * XBUF * 8u, g1 + (long)s * NSTR);
        }
        cp_commit();
    }

    // ---- stage weights gmem -> smem (coalesced) -> registers (swizzled) ----
    // per round r (= c): [p(4)][yv(16)][j(8)] float4, swizzle j^(yv&7)
    u64 w2[32];
    for (int r = 0; r < 4; ++r) {
        __syncthreads();
#pragma unroll
        for (int k = 0; k < 4; ++k) {
            int G   = k * 128 + tid;       // 0..511
            int p   = G >> 7;
            int yy  = (G >> 3) & 15;
            int j   = G & 7;
            float4 v = __ldg((const float4*)W +
                             (((r * 4 + p) * 16384 + xp * 128 + y0 + yy) * 8 + j));
            smw[p * 128 + yy * 8 + (j ^ (yy & 7))] = v;
        }
        __syncthreads();
        if (c == r) {
#pragma unroll
            for (int pp = 0; pp < 2; ++pp) {
                int p = 2 * ph + pp;
#pragma unroll
                for (int t = 0; t < 8; ++t) {
                    float4 v = smw[p * 128 + yv * 8 + (t ^ (yv & 7))];
                    w2[pp * 16 + 2 * t]     = pk2(v.x, v.y);
                    w2[pp * 16 + 2 * t + 1] = pk2(v.z, v.w);
                }
            }
        }
    }

    // bias/output channel this lane writes: pw = 2ph + (c&1), valid for c<2
    const int pw = 2 * ph + (c & 1);
    const float2 bz = *(const float2*)(B + ((pw * 128 + xp) * 128 + y) * 2);
    const int OSTR = 4 * 2 * 16384;
    int oo = ((n0 * 4 + pw) * 2) * 16384 + xp * 128 + y;   // += OSTR per slice

    // consumer smem bases (float2 units): plane (c,ir), column yv^sw(c)
    const int swc = ((c & 1) << 3) | ((c >> 1) << 1);
    const int xb  = c * 64 + (yv ^ swc);    // + ir*16

    // moving refill pointers: window w refills slices 4w+8..4w+11
    const float2* gr0 = (const float2*)X + (long)n0 * NSTR + goff0 + 8L * NSTR;
    const float2* gr1 = (const float2*)X + (long)n0 * NSTR + goff1 + 8L * NSTR;

#pragma unroll 4
    for (int w = 0; w < NPC / 4; ++w) {
        const int s0 = 4 * w;

        // refill BEFORE wait/sync (targets disjoint from windows w-1..w+1)
        if (w < NPC / 4 - 2) {
#pragma unroll
            for (int j = 0; j < 4; ++j) {
                cp8(sa0 + (unsigned)((s0 + 8 + j) & 15) * XBUF * 8u, gr0 + (long)j * NSTR);
                cp8(sa1 + (unsigned)((s0 + 8 + j) & 15) * XBUF * 8u, gr1 + (long)j * NSTR);
            }
        }
        cp_commit();
        gr0 += 4L * NSTR;
        gr1 += 4L * NSTR;

        cp_wait1();          // group holding this window's slices has landed
        __syncthreads();     // visible; retires window w-1's reads

#pragma unroll
        for (int q = 0; q < 4; ++q) {
            const float2* buf = xsm + ((s0 + q) & 15) * XBUF + xb;
            float2 A0 = buf[0];    // (a0,e0)  ir=0
            float2 A1 = buf[16];   // (b0,f0)  ir=1
            float2 A2 = buf[32];   // (a1,e1)  ir=2
            float2 A3 = buf[48];   // (b1,f1)  ir=3

            const float a0 = A0.x, e0 = A0.y, b0 = A1.x, f0 = A1.y;
            const float a1 = A2.x, e1 = A2.y, b1 = A3.x, f1 = A3.y;

            u64 ab2[4] = { pk2(a0*b0,a0*b0), pk2(a0*b1,a0*b1),
                           pk2(a1*b0,a1*b0), pk2(a1*b1,a1*b1) };
            u64 ef2[4] = { pk2(e0*f0,e0*f0), pk2(e0*f1,e0*f1),
                           pk2(e1*f0,e1*f0), pk2(e1*f1,e1*f1) };

            // two fma trees (p = 2ph, 2ph+1) share the patch products
            u64 acc0, acc1;
#pragma unroll
            for (int g = 0; g < 4; ++g) {
                u64 t0 = mul2(w2[g*4+0], ef2[0]);
                fma2(t0, w2[g*4+1], ef2[1]);
                fma2(t0, w2[g*4+2], ef2[2]);
                fma2(t0, w2[g*4+3], ef2[3]);
                u64 t1 = mul2(w2[16+g*4+0], ef2[0]);
                fma2(t1, w2[16+g*4+1], ef2[1]);
                fma2(t1, w2[16+g*4+2], ef2[2]);
                fma2(t1, w2[16+g*4+3], ef2[3]);
                if (g == 0) { acc0 = mul2(ab2[0], t0); acc1 = mul2(ab2[0], t1); }
                else        { fma2(acc0, ab2[g], t0); fma2(acc1, ab2[g], t1); }
            }

            // reduce over c: butterfly xor 8 then xor 16
            acc0 = add2(acc0, __shfl_xor_sync(0xffffffffu, acc0, 8));
            acc1 = add2(acc1, __shfl_xor_sync(0xffffffffu, acc1, 8));
            acc0 = add2(acc0, __shfl_xor_sync(0xffffffffu, acc0, 16));
            acc1 = add2(acc1, __shfl_xor_sync(0xffffffffu, acc1, 16));

            if (c < 2) {
                u64 val = (c == 0) ? acc0 : acc1;
                float r0, r1; up2(val, r0, r1);
                O[oo]         = r0 + bz.x;
                O[oo + 16384] = r1 + bz.y;
            }
            oo += OSTR;
        }
    }
}

extern "C" void kernel_launch(void* const* d_in, const int* in_sizes, int n_in,
                              void* d_out, int out_size)
{
    const float* X = (const float*)d_in[0];   // x        (64,4,2,256,256)
    const float* W = (const float*)d_in[1];   // tensors  (4,4,128,128,2,2,2,2,2)
    const float* B = (const float*)d_in[2];   // bias     (4,128,128,2)
    float* O = (float*)d_out;                 // out      (64,4,2,128,128)
    (void)in_sizes; (void)n_in; (void)out_size;
    ttn_kernel<<<128 * 8 * NCHUNK, 128>>>(X, W, B, O);
}